// round 12
// baseline (speedup 1.0000x reference)
#include <cuda_runtime.h>
#include <cuda_fp16.h>
#include <math.h>
#include <stdint.h>

#define T_TOK   2048
#define HDIM    2048
#define NEXP    8
#define IDIM    5632
#define TWOI    11264
#define NASSIGN 4096
#define MAXT    40
#define PADROWS (NASSIGN + 256)

#define BM 128
#define BN 256
#define BK 32
#define PITCH 40                      // fp16 elems per tile row (80B), conflict-free
#define FPITCHB 144                   // fp32 staging pitch (bytes)

// smem layout (bytes): A fp16 tiles double-buffered, B fp16 tile, B fp32 staging
#define AT0 0
#define AT1 10240
#define BT  20480
#define FBo 40960
#define SMEM_BYTES 77824

// ---------------- routing / scheduling state ----------------
__device__ int   g_perm_token[NASSIGN];
__device__ float g_perm_gate[NASSIGN];
__device__ int   g_se[MAXT], g_sm0[MAXT], g_srows[MAXT];

// ---------------- fp16 operands / scratch ----------------
__device__ __align__(128) __half g_af[(size_t)PADROWS * HDIM];   // gathered X, fp16
__device__ __align__(128) __half g_h [(size_t)PADROWS * IDIM];   // activation, fp16

// ================= helpers =================
__device__ __forceinline__ uint32_t smem_to_u32(const void* p) {
    uint32_t a;
    asm("{ .reg .u64 t; cvta.to.shared.u64 t, %1; cvt.u32.u64 %0, t; }" : "=r"(a) : "l"(p));
    return a;
}
__device__ __forceinline__ void cp16(uint32_t dst, const void* src) {
    asm volatile("cp.async.cg.shared.global [%0], [%1], 16;" :: "r"(dst), "l"(src));
}
__device__ __forceinline__ void ldsm4(uint32_t* r, uint32_t addr) {
    asm volatile("ldmatrix.sync.aligned.m8n8.x4.shared.b16 {%0,%1,%2,%3}, [%4];"
                 : "=r"(r[0]), "=r"(r[1]), "=r"(r[2]), "=r"(r[3]) : "r"(addr));
}
__device__ __forceinline__ void mma16816(float* d, const uint32_t* a, const uint32_t* b) {
    asm volatile(
        "mma.sync.aligned.m16n8k16.row.col.f32.f16.f16.f32 "
        "{%0,%1,%2,%3}, {%4,%5,%6,%7}, {%8,%9}, {%0,%1,%2,%3};"
        : "+f"(d[0]), "+f"(d[1]), "+f"(d[2]), "+f"(d[3])
        : "r"(a[0]), "r"(a[1]), "r"(a[2]), "r"(a[3]), "r"(b[0]), "r"(b[1]));
}
__device__ __forceinline__ void lds128f(float4& v, uint32_t a) {
    asm volatile("ld.shared.v4.f32 {%0,%1,%2,%3}, [%4];"
                 : "=f"(v.x), "=f"(v.y), "=f"(v.z), "=f"(v.w) : "r"(a));
}
__device__ __forceinline__ void sts128(uint32_t a, uint32_t x, uint32_t y, uint32_t z, uint32_t w) {
    asm volatile("st.shared.v4.b32 [%0], {%1,%2,%3,%4};" :: "r"(a), "r"(x), "r"(y), "r"(z), "r"(w));
}
__device__ __forceinline__ uint32_t cvt2(float f0, float f1) {
    __half2 hh = __floats2half2_rn(f0, f1);
    return *(uint32_t*)&hh;
}

// ================= routing =================
__global__ void route_kernel(const float* __restrict__ logits)
{
    __shared__ int s_cnt[NEXP], s_off[NEXP + 1], s_cur[NEXP];
    const int tid = threadIdx.x;
    if (tid < NEXP) s_cnt[tid] = 0;
    __syncthreads();
    for (int t = tid; t < T_TOK; t += blockDim.x) {
        const float* l = logits + t * NEXP;
        int i1 = 0; float v1 = l[0];
        #pragma unroll
        for (int e = 1; e < NEXP; e++) { float v = l[e]; if (v > v1) { v1 = v; i1 = e; } }
        int i2 = -1; float v2 = -3.0e38f;
        #pragma unroll
        for (int e = 0; e < NEXP; e++) { if (e == i1) continue; float v = l[e]; if (v > v2) { v2 = v; i2 = e; } }
        atomicAdd(&s_cnt[i1], 1); atomicAdd(&s_cnt[i2], 1);
    }
    __syncthreads();
    if (tid == 0) {
        int acc = 0;
        for (int e = 0; e < NEXP; e++) { s_off[e] = acc; s_cur[e] = acc; acc += s_cnt[e]; }
        s_off[NEXP] = acc;
    }
    __syncthreads();
    for (int t = tid; t < T_TOK; t += blockDim.x) {
        const float* l = logits + t * NEXP;
        int i1 = 0; float v1 = l[0];
        #pragma unroll
        for (int e = 1; e < NEXP; e++) { float v = l[e]; if (v > v1) { v1 = v; i1 = e; } }
        int i2 = -1; float v2 = -3.0e38f;
        #pragma unroll
        for (int e = 0; e < NEXP; e++) { if (e == i1) continue; float v = l[e]; if (v > v2) { v2 = v; i2 = e; } }
        float g1 = 1.0f / (1.0f + expf(v2 - v1));
        float g2 = 1.0f - g1;
        int s1 = atomicAdd(&s_cur[i1], 1);
        g_perm_token[s1] = t; g_perm_gate[s1] = g1;
        int s2 = atomicAdd(&s_cur[i2], 1);
        g_perm_token[s2] = t; g_perm_gate[s2] = g2;
    }
    __syncthreads();
    if (tid == 0) {
        int nt = 0;
        for (int e = 0; e < NEXP; e++) {
            int off = s_off[e], cnt = s_cnt[e];
            for (int r = 0; r < cnt; r += BM) {
                g_se[nt] = e; g_sm0[nt] = off + r;
                g_srows[nt] = (cnt - r < BM) ? (cnt - r) : BM; nt++;
            }
        }
        for (; nt < MAXT; nt++) g_srows[nt] = 0;
    }
}

__global__ void zero_kernel(float4* __restrict__ out)
{
    int idx = blockIdx.x * blockDim.x + threadIdx.x;
    if (idx < (T_TOK * HDIM) / 4) out[idx] = make_float4(0.f, 0.f, 0.f, 0.f);
}

// gather X rows by perm token -> fp16
__global__ void permA_kernel(const float* __restrict__ X)
{
    int idx = blockIdx.x * blockDim.x + threadIdx.x;
    if (idx >= NASSIGN * HDIM / 4) return;
    int r = idx / (HDIM / 4);
    int c = (idx % (HDIM / 4)) * 4;
    int t = g_perm_token[r];
    float4 x = *(const float4*)(X + (size_t)t * HDIM + c);
    uint2 p; p.x = cvt2(x.x, x.y); p.y = cvt2(x.z, x.w);
    *(uint2*)(g_af + (size_t)r * HDIM + c) = p;
}

// ======== shared mainloop building blocks ========
// convert FB fp32 staging (256 rows) -> fp16 B tile
__device__ __forceinline__ void convert_B(uint32_t sb, int tid)
{
    #pragma unroll
    for (int j = 0; j < 2; j++) {
        int g = tid + j * 512;
        int r = g >> 2, kg = g & 3;
        uint32_t fb = sb + FBo + r * FPITCHB + kg * 32;
        float4 x0, x1; lds128f(x0, fb); lds128f(x1, fb + 16);
        uint32_t d = sb + BT + (r * PITCH + kg * 8) * 2;
        sts128(d, cvt2(x0.x, x0.y), cvt2(x0.z, x0.w), cvt2(x1.x, x1.y), cvt2(x1.z, x1.w));
    }
}

// ============ GEMM1: h = silu(X@Wg^T) * (X@Wu^T), fused epilogue ============
// grid: (MAXT, IDIM/128). Each CTA: 128 M-rows x 128 h-cols (256 B rows: g+u pairs)
__global__ __launch_bounds__(512, 1) void gemm1_fused(const float* __restrict__ W13)
{
    constexpr int KD = HDIM;
    constexpr int NCH = KD / BK;        // 64 stages

    const int bt    = blockIdx.x;
    const int mrows = g_srows[bt];
    if (mrows == 0) return;
    const int e   = g_se[bt];
    const int m0  = g_sm0[bt];
    const int n0g = blockIdx.y * 128;   // h-column block
    const float* Bw = W13 + (size_t)e * TWOI * KD;

    extern __shared__ char smem[];
    const uint32_t sb = smem_to_u32(smem);
    const int tid  = threadIdx.x;
    const int wid  = tid >> 5;
    const int lane = tid & 31;
    const int wm   = (wid & 3) << 5;
    const int wn   = (wid >> 2) << 6;   // warp's B-smem-row offset

    // ---- A cp.async endpoint (fp16 direct into tile): 1 chunk/thread ----
    const __half* srcA = g_af + (size_t)(m0 + (tid >> 2)) * KD + (tid & 3) * 8;
    const uint32_t dA  = ((tid >> 2) * PITCH + (tid & 3) * 8) * 2;

    // ---- B fp32 staging endpoints: 4 rows/thread, g/u interleaved mapping ----
    // smem row r: wg = r>>6, inner = r&63; inner<32 -> g col, else u col (+IDIM)
    const float* srcB[4];
    {
        int rbase = tid >> 3, cg = (tid & 7) * 4;
        #pragma unroll
        for (int j = 0; j < 4; j++) {
            int r = rbase + j * 64;
            int wg = r >> 6, inner = r & 63;
            int grow = (inner < 32) ? (n0g + wg * 32 + inner)
                                    : (IDIM + n0g + wg * 32 + inner - 32);
            srcB[j] = Bw + (size_t)grow * KD + cg;
        }
    }
    const uint32_t dB = sb + FBo + (tid >> 3) * FPITCHB + (tid & 7) * 16;

    const uint32_t a_off = ((wm + (lane & 15)) * PITCH + ((lane >> 4) << 3)) * 2;
    const uint32_t b_off = ((wn + ((lane >> 4) << 3) + (lane & 7)) * PITCH + (((lane >> 3) & 1) << 3)) * 2;

    float acc[2][8][4];
    #pragma unroll
    for (int i = 0; i < 2; i++)
        #pragma unroll
        for (int j = 0; j < 8; j++)
            #pragma unroll
            for (int q = 0; q < 4; q++) acc[i][j][q] = 0.f;

    // prologue
    cp16(sb + AT0 + dA, srcA);
    #pragma unroll
    for (int j = 0; j < 4; j++) cp16(dB + j * 64 * FPITCHB, srcB[j]);
    asm volatile("cp.async.commit_group;" ::: "memory");
    srcA += BK;
    #pragma unroll
    for (int j = 0; j < 4; j++) srcB[j] += BK;

    for (int i = 0; i < NCH; i++) {
        const uint32_t at = sb + ((i & 1) ? AT1 : AT0);
        asm volatile("cp.async.wait_group 0;" ::: "memory");
        __syncthreads();
        convert_B(sb, tid);
        __syncthreads();
        if (i + 1 < NCH) {
            cp16(sb + (((i + 1) & 1) ? AT1 : AT0) + dA, srcA);
            #pragma unroll
            for (int j = 0; j < 4; j++) cp16(dB + j * 64 * FPITCHB, srcB[j]);
            srcA += BK;
            #pragma unroll
            for (int j = 0; j < 4; j++) srcB[j] += BK;
        }
        asm volatile("cp.async.commit_group;" ::: "memory");

        #pragma unroll
        for (int ks = 0; ks < BK; ks += 16) {
            uint32_t afr[2][4], bfr[4][4];
            ldsm4(afr[0], at + a_off + ks * 2);
            ldsm4(afr[1], at + a_off + (16 * PITCH + ks) * 2);
            #pragma unroll
            for (int jn = 0; jn < 4; jn++)
                ldsm4(bfr[jn], sb + BT + b_off + (jn * 16 * PITCH + ks) * 2);
            #pragma unroll
            for (int im = 0; im < 2; im++)
                #pragma unroll
                for (int jn = 0; jn < 4; jn++) {
                    mma16816(acc[im][2 * jn],     afr[im], &bfr[jn][0]);
                    mma16816(acc[im][2 * jn + 1], afr[im], &bfr[jn][2]);
                }
        }
    }

    // ---- fused epilogue: h = silu(g)*u, write fp16 ----
    // acc[im][0..3] = g cols, acc[im][4..7] = u cols (same columns)
    const int wg32 = (wn >> 6) * 32;
    #pragma unroll
    for (int im = 0; im < 2; im++) {
        #pragma unroll
        for (int half = 0; half < 2; half++) {
            const int rloc = wm + im * 16 + half * 8 + (lane >> 2);
            if (rloc >= mrows) continue;
            __half* hrow = g_h + (size_t)(m0 + rloc) * IDIM + n0g + wg32;
            #pragma unroll
            for (int jn8 = 0; jn8 < 4; jn8++) {
                const float gv0 = acc[im][jn8][half * 2 + 0];
                const float gv1 = acc[im][jn8][half * 2 + 1];
                const float uv0 = acc[im][jn8 + 4][half * 2 + 0];
                const float uv1 = acc[im][jn8 + 4][half * 2 + 1];
                const float h0 = gv0 / (1.0f + expf(-gv0)) * uv0;
                const float h1 = gv1 / (1.0f + expf(-gv1)) * uv1;
                const int col = jn8 * 8 + ((lane & 3) << 1);
                *(uint32_t*)(hrow + col) = cvt2(h0, h1);
            }
        }
    }
}

// ============ GEMM2: out += gate * (h @ W2^T), split-K, in-kernel B cvt ============
#define KSPLIT2 2
__global__ __launch_bounds__(512, 1) void gemm2_fused(
    const float* __restrict__ W2, float* __restrict__ outp)
{
    constexpr int KD = IDIM;
    constexpr int NCH = KD / (BK * KSPLIT2);   // 88 stages

    const int bt    = blockIdx.x;
    const int mrows = g_srows[bt];
    if (mrows == 0) return;
    const int e   = g_se[bt];
    const int m0  = g_sm0[bt];
    const int n0  = blockIdx.y * BN;
    const int kk0 = blockIdx.z * (KD / KSPLIT2);
    const float* Bw = W2 + (size_t)e * HDIM * KD;

    extern __shared__ char smem[];
    const uint32_t sb = smem_to_u32(smem);
    const int tid  = threadIdx.x;
    const int wid  = tid >> 5;
    const int lane = tid & 31;
    const int wm   = (wid & 3) << 5;
    const int wn   = (wid >> 2) << 6;

    const __half* srcA = g_h + (size_t)(m0 + (tid >> 2)) * KD + kk0 + (tid & 3) * 8;
    const uint32_t dA  = ((tid >> 2) * PITCH + (tid & 3) * 8) * 2;
    const float* srcB0 = Bw + (size_t)(n0 + (tid >> 3)) * KD + kk0 + (tid & 7) * 4;
    const uint32_t dB  = sb + FBo + (tid >> 3) * FPITCHB + (tid & 7) * 16;

    const uint32_t a_off = ((wm + (lane & 15)) * PITCH + ((lane >> 4) << 3)) * 2;
    const uint32_t b_off = ((wn + ((lane >> 4) << 3) + (lane & 7)) * PITCH + (((lane >> 3) & 1) << 3)) * 2;

    float acc[2][8][4];
    #pragma unroll
    for (int i = 0; i < 2; i++)
        #pragma unroll
        for (int j = 0; j < 8; j++)
            #pragma unroll
            for (int q = 0; q < 4; q++) acc[i][j][q] = 0.f;

    cp16(sb + AT0 + dA, srcA);
    #pragma unroll
    for (int j = 0; j < 4; j++) cp16(dB + j * 64 * FPITCHB, srcB0 + (size_t)j * 64 * KD);
    asm volatile("cp.async.commit_group;" ::: "memory");
    srcA += BK; srcB0 += BK;

    for (int i = 0; i < NCH; i++) {
        const uint32_t at = sb + ((i & 1) ? AT1 : AT0);
        asm volatile("cp.async.wait_group 0;" ::: "memory");
        __syncthreads();
        convert_B(sb, tid);
        __syncthreads();
        if (i + 1 < NCH) {
            cp16(sb + (((i + 1) & 1) ? AT1 : AT0) + dA, srcA);
            #pragma unroll
            for (int j = 0; j < 4; j++) cp16(dB + j * 64 * FPITCHB, srcB0 + (size_t)j * 64 * KD);
            srcA += BK; srcB0 += BK;
        }
        asm volatile("cp.async.commit_group;" ::: "memory");

        #pragma unroll
        for (int ks = 0; ks < BK; ks += 16) {
            uint32_t afr[2][4], bfr[4][4];
            ldsm4(afr[0], at + a_off + ks * 2);
            ldsm4(afr[1], at + a_off + (16 * PITCH + ks) * 2);
            #pragma unroll
            for (int jn = 0; jn < 4; jn++)
                ldsm4(bfr[jn], sb + BT + b_off + (jn * 16 * PITCH + ks) * 2);
            #pragma unroll
            for (int im = 0; im < 2; im++)
                #pragma unroll
                for (int jn = 0; jn < 4; jn++) {
                    mma16816(acc[im][2 * jn],     afr[im], &bfr[jn][0]);
                    mma16816(acc[im][2 * jn + 1], afr[im], &bfr[jn][2]);
                }
        }
    }

    // gated atomic-add epilogue
    #pragma unroll
    for (int im = 0; im < 2; im++) {
        #pragma unroll
        for (int half = 0; half < 2; half++) {
            const int rloc = wm + im * 16 + half * 8 + (lane >> 2);
            if (rloc >= mrows) continue;
            const int   tok  = g_perm_token[m0 + rloc];
            const float gate = g_perm_gate[m0 + rloc];
            #pragma unroll
            for (int jn8 = 0; jn8 < 8; jn8++) {
                const int col = n0 + wn + jn8 * 8 + ((lane & 3) << 1);
                float* dst = outp + (size_t)tok * HDIM + col;
                atomicAdd(dst + 0, gate * acc[im][jn8][half * 2 + 0]);
                atomicAdd(dst + 1, gate * acc[im][jn8][half * 2 + 1]);
            }
        }
    }
}

// ================= launch =================
extern "C" void kernel_launch(void* const* d_in, const int* in_sizes, int n_in,
                              void* d_out, int out_size)
{
    const float* hs     = (const float*)d_in[0];
    const float* logits = (const float*)d_in[1];
    const float* w13    = (const float*)d_in[2];
    const float* w2     = (const float*)d_in[3];
    float* out = (float*)d_out;

    cudaFuncSetAttribute(gemm1_fused, cudaFuncAttributeMaxDynamicSharedMemorySize, SMEM_BYTES);
    cudaFuncSetAttribute(gemm2_fused, cudaFuncAttributeMaxDynamicSharedMemorySize, SMEM_BYTES);

    zero_kernel<<<(T_TOK * HDIM / 4 + 255) / 256, 256>>>((float4*)out);
    route_kernel<<<1, 256>>>(logits);
    permA_kernel<<<(NASSIGN * HDIM / 4 + 255) / 256, 256>>>(hs);

    gemm1_fused<<<dim3(MAXT, IDIM / 128), 512, SMEM_BYTES>>>(w13);
    gemm2_fused<<<dim3(MAXT, HDIM / BN, KSPLIT2), 512, SMEM_BYTES>>>(w2, out);
}

// round 13
// speedup vs baseline: 1.1510x; 1.1510x over previous
#include <cuda_runtime.h>
#include <cuda_fp16.h>
#include <math.h>
#include <stdint.h>

#define T_TOK   2048
#define HDIM    2048
#define NEXP    8
#define IDIM    5632
#define TWOI    11264
#define NASSIGN 4096
#define MAXT    40
#define PADROWS (NASSIGN + 256)

#define BM 128
#define BN 256
#define BK 32
#define PITCH 40                      // fp16 elems per smem row (80B), conflict-free
#define ASZ (BM * PITCH * 2)          // 10240 B
#define BSZ (BN * PITCH * 2)          // 20480 B
#define STAGE (ASZ + BSZ)             // 30720 B
#define SMEM_BYTES (2 * STAGE)        // 61440 B

// ---------------- routing / scheduling state ----------------
__device__ int   g_perm_token[NASSIGN];
__device__ float g_perm_gate[NASSIGN];
__device__ int   g_se[MAXT], g_sm0[MAXT], g_srows[MAXT];

// ---------------- fp16 operands / scratch ----------------
__device__ __align__(128) __half g_af  [(size_t)PADROWS * HDIM];       // gathered X fp16
__device__ __align__(128) __half g_w13f[(size_t)NEXP * TWOI * HDIM];   // w13 fp16
__device__ __align__(128) __half g_w2f [(size_t)NEXP * HDIM * IDIM];   // w2 fp16
__device__ __align__(128) __half g_h   [(size_t)PADROWS * IDIM];       // activation fp16

// ================= helpers =================
__device__ __forceinline__ uint32_t smem_to_u32(const void* p) {
    uint32_t a;
    asm("{ .reg .u64 t; cvta.to.shared.u64 t, %1; cvt.u32.u64 %0, t; }" : "=r"(a) : "l"(p));
    return a;
}
__device__ __forceinline__ void cp16(uint32_t dst, const void* src) {
    asm volatile("cp.async.cg.shared.global [%0], [%1], 16;" :: "r"(dst), "l"(src));
}
__device__ __forceinline__ void ldsm4(uint32_t* r, uint32_t addr) {
    asm volatile("ldmatrix.sync.aligned.m8n8.x4.shared.b16 {%0,%1,%2,%3}, [%4];"
                 : "=r"(r[0]), "=r"(r[1]), "=r"(r[2]), "=r"(r[3]) : "r"(addr));
}
__device__ __forceinline__ void mma16816(float* d, const uint32_t* a, const uint32_t* b) {
    asm volatile(
        "mma.sync.aligned.m16n8k16.row.col.f32.f16.f16.f32 "
        "{%0,%1,%2,%3}, {%4,%5,%6,%7}, {%8,%9}, {%0,%1,%2,%3};"
        : "+f"(d[0]), "+f"(d[1]), "+f"(d[2]), "+f"(d[3])
        : "r"(a[0]), "r"(a[1]), "r"(a[2]), "r"(a[3]), "r"(b[0]), "r"(b[1]));
}
__device__ __forceinline__ uint32_t cvt2(float f0, float f1) {
    __half2 hh = __floats2half2_rn(f0, f1);
    return *(uint32_t*)&hh;
}

// ================= routing =================
__global__ void route_kernel(const float* __restrict__ logits)
{
    __shared__ int s_cnt[NEXP], s_off[NEXP + 1], s_cur[NEXP];
    const int tid = threadIdx.x;
    if (tid < NEXP) s_cnt[tid] = 0;
    __syncthreads();
    for (int t = tid; t < T_TOK; t += blockDim.x) {
        const float* l = logits + t * NEXP;
        int i1 = 0; float v1 = l[0];
        #pragma unroll
        for (int e = 1; e < NEXP; e++) { float v = l[e]; if (v > v1) { v1 = v; i1 = e; } }
        int i2 = -1; float v2 = -3.0e38f;
        #pragma unroll
        for (int e = 0; e < NEXP; e++) { if (e == i1) continue; float v = l[e]; if (v > v2) { v2 = v; i2 = e; } }
        atomicAdd(&s_cnt[i1], 1); atomicAdd(&s_cnt[i2], 1);
    }
    __syncthreads();
    if (tid == 0) {
        int acc = 0;
        for (int e = 0; e < NEXP; e++) { s_off[e] = acc; s_cur[e] = acc; acc += s_cnt[e]; }
        s_off[NEXP] = acc;
    }
    __syncthreads();
    for (int t = tid; t < T_TOK; t += blockDim.x) {
        const float* l = logits + t * NEXP;
        int i1 = 0; float v1 = l[0];
        #pragma unroll
        for (int e = 1; e < NEXP; e++) { float v = l[e]; if (v > v1) { v1 = v; i1 = e; } }
        int i2 = -1; float v2 = -3.0e38f;
        #pragma unroll
        for (int e = 0; e < NEXP; e++) { if (e == i1) continue; float v = l[e]; if (v > v2) { v2 = v; i2 = e; } }
        float g1 = 1.0f / (1.0f + expf(v2 - v1));
        float g2 = 1.0f - g1;
        int s1 = atomicAdd(&s_cur[i1], 1);
        g_perm_token[s1] = t; g_perm_gate[s1] = g1;
        int s2 = atomicAdd(&s_cur[i2], 1);
        g_perm_token[s2] = t; g_perm_gate[s2] = g2;
    }
    __syncthreads();
    if (tid == 0) {
        int nt = 0;
        for (int e = 0; e < NEXP; e++) {
            int off = s_off[e], cnt = s_cnt[e];
            for (int r = 0; r < cnt; r += BM) {
                g_se[nt] = e; g_sm0[nt] = off + r;
                g_srows[nt] = (cnt - r < BM) ? (cnt - r) : BM; nt++;
            }
        }
        for (; nt < MAXT; nt++) g_srows[nt] = 0;
    }
}

__global__ void zero_kernel(float4* __restrict__ out)
{
    int idx = blockIdx.x * blockDim.x + threadIdx.x;
    if (idx < (T_TOK * HDIM) / 4) out[idx] = make_float4(0.f, 0.f, 0.f, 0.f);
}

// gather X rows by perm token -> fp16
__global__ void permA_kernel(const float* __restrict__ X)
{
    int idx = blockIdx.x * blockDim.x + threadIdx.x;
    if (idx >= NASSIGN * HDIM / 4) return;
    int r = idx / (HDIM / 4);
    int c = (idx % (HDIM / 4)) * 4;
    int t = g_perm_token[r];
    float4 x = *(const float4*)(X + (size_t)t * HDIM + c);
    uint2 p; p.x = cvt2(x.x, x.y); p.y = cvt2(x.z, x.w);
    *(uint2*)(g_af + (size_t)r * HDIM + c) = p;
}

// flat fp32 -> fp16 weight conversion. WHICH: 0 = w13, 1 = w2.
template<int WHICH>
__global__ void cvt16_kernel(const float4* __restrict__ src, size_t n4)
{
    __half* dst = (WHICH == 0) ? g_w13f : g_w2f;
    size_t idx = (size_t)blockIdx.x * blockDim.x + threadIdx.x;
    if (idx >= n4) return;
    float4 x = src[idx];
    uint2 p; p.x = cvt2(x.x, x.y); p.y = cvt2(x.z, x.w);
    *(uint2*)(dst + idx * 4) = p;
}

// ============ GEMM1: fused h = silu(X@Wg^T)*(X@Wu^T), pure fp16 mainloop ============
// grid (MAXT, IDIM/128). B smem rows r: wg=r>>6, inner=r&63;
// inner<32 -> g-row n0g+wg*32+inner, else u-row IDIM+n0g+wg*32+inner-32.
__global__ __launch_bounds__(512, 1) void gemm1_fused(float* __restrict__ dummy)
{
    constexpr int KD = HDIM;
    constexpr int NCH = KD / BK;       // 64 stages

    const int bt    = blockIdx.x;
    const int mrows = g_srows[bt];
    if (mrows == 0) return;
    const int e   = g_se[bt];
    const int m0  = g_sm0[bt];
    const int n0g = blockIdx.y * 128;
    const __half* Bf = g_w13f + (size_t)e * TWOI * KD;

    extern __shared__ char smem[];
    const uint32_t sb0 = smem_to_u32(smem);
    const int tid  = threadIdx.x;
    const int wid  = tid >> 5;
    const int lane = tid & 31;
    const int wm   = (wid & 3) << 5;
    const int wn   = (wid >> 2) << 6;

    // ---- load endpoints (fp16 direct into tiles) ----
    const __half* srcA = g_af + (size_t)(m0 + (tid >> 2)) * KD + (tid & 3) * 8;
    const uint32_t dA  = ((tid >> 2) * PITCH + (tid & 3) * 8) * 2;
    const __half* srcB[2];
    uint32_t dBo[2];
    #pragma unroll
    for (int j = 0; j < 2; j++) {
        int idx = j * 512 + tid;
        int row = idx >> 2, kg = idx & 3;
        int wg = row >> 6, inner = row & 63;
        int grow = (inner < 32) ? (n0g + wg * 32 + inner)
                                : (IDIM + n0g + wg * 32 + inner - 32);
        srcB[j] = Bf + (size_t)grow * KD + kg * 8;
        dBo[j]  = ASZ + (row * PITCH + kg * 8) * 2;
    }

    const uint32_t a_off = ((wm + (lane & 15)) * PITCH + ((lane >> 4) << 3)) * 2;
    const uint32_t b_off = ASZ + ((wn + ((lane >> 4) << 3) + (lane & 7)) * PITCH + (((lane >> 3) & 1) << 3)) * 2;

    float acc[2][8][4];
    #pragma unroll
    for (int i = 0; i < 2; i++)
        #pragma unroll
        for (int j = 0; j < 8; j++)
            #pragma unroll
            for (int q = 0; q < 4; q++) acc[i][j][q] = 0.f;

    // prologue
    cp16(sb0 + dA, srcA);
    cp16(sb0 + dBo[0], srcB[0]);
    cp16(sb0 + dBo[1], srcB[1]);
    asm volatile("cp.async.commit_group;" ::: "memory");
    srcA += BK; srcB[0] += BK; srcB[1] += BK;

    for (int i = 0; i < NCH; i++) {
        const int b = i & 1;
        if (i + 1 < NCH) {
            const uint32_t sn = sb0 + (1 - b) * STAGE;
            cp16(sn + dA, srcA);
            cp16(sn + dBo[0], srcB[0]);
            cp16(sn + dBo[1], srcB[1]);
            asm volatile("cp.async.commit_group;" ::: "memory");
            srcA += BK; srcB[0] += BK; srcB[1] += BK;
            asm volatile("cp.async.wait_group 1;" ::: "memory");
        } else {
            asm volatile("cp.async.wait_group 0;" ::: "memory");
        }
        __syncthreads();

        const uint32_t sa = sb0 + b * STAGE;
        #pragma unroll
        for (int ks = 0; ks < BK; ks += 16) {
            uint32_t afr[2][4], bfr[4][4];
            ldsm4(afr[0], sa + a_off + ks * 2);
            ldsm4(afr[1], sa + a_off + (16 * PITCH + ks) * 2);
            #pragma unroll
            for (int jn = 0; jn < 4; jn++)
                ldsm4(bfr[jn], sa + b_off + (jn * 16 * PITCH + ks) * 2);
            #pragma unroll
            for (int im = 0; im < 2; im++)
                #pragma unroll
                for (int jn = 0; jn < 4; jn++) {
                    mma16816(acc[im][2 * jn],     afr[im], &bfr[jn][0]);
                    mma16816(acc[im][2 * jn + 1], afr[im], &bfr[jn][2]);
                }
        }
        __syncthreads();
    }

    // ---- fused epilogue: h = silu(g)*u -> fp16 g_h ----
    const int wg32 = (wn >> 6) * 32;
    #pragma unroll
    for (int im = 0; im < 2; im++) {
        #pragma unroll
        for (int half = 0; half < 2; half++) {
            const int rloc = wm + im * 16 + half * 8 + (lane >> 2);
            if (rloc >= mrows) continue;
            __half* hrow = g_h + (size_t)(m0 + rloc) * IDIM + n0g + wg32;
            #pragma unroll
            for (int jn8 = 0; jn8 < 4; jn8++) {
                const float gv0 = acc[im][jn8][half * 2 + 0];
                const float gv1 = acc[im][jn8][half * 2 + 1];
                const float uv0 = acc[im][jn8 + 4][half * 2 + 0];
                const float uv1 = acc[im][jn8 + 4][half * 2 + 1];
                const float h0 = gv0 / (1.0f + expf(-gv0)) * uv0;
                const float h1 = gv1 / (1.0f + expf(-gv1)) * uv1;
                const int col = jn8 * 8 + ((lane & 3) << 1);
                *(uint32_t*)(hrow + col) = cvt2(h0, h1);
            }
        }
    }
    if (dummy) *dummy = 0.f;   // never taken; keeps signature uniform
}

// ============ GEMM2: out += gate*(h @ W2f^T), pure fp16, split-K ============
#define KSPLIT2 2
__global__ __launch_bounds__(512, 1) void gemm2_f16(float* __restrict__ outp)
{
    constexpr int KD = IDIM;
    constexpr int NCH = KD / (BK * KSPLIT2);

    const int bt    = blockIdx.x;
    const int mrows = g_srows[bt];
    if (mrows == 0) return;
    const int e   = g_se[bt];
    const int m0  = g_sm0[bt];
    const int n0  = blockIdx.y * BN;
    const int kk0 = blockIdx.z * (KD / KSPLIT2);
    const __half* Bf = g_w2f + (size_t)e * HDIM * KD;

    extern __shared__ char smem[];
    const uint32_t sb0 = smem_to_u32(smem);
    const int tid  = threadIdx.x;
    const int wid  = tid >> 5;
    const int lane = tid & 31;
    const int wm   = (wid & 3) << 5;
    const int wn   = (wid >> 2) << 6;

    const __half* srcA = g_h + (size_t)(m0 + (tid >> 2)) * KD + kk0 + (tid & 3) * 8;
    const uint32_t dA  = ((tid >> 2) * PITCH + (tid & 3) * 8) * 2;
    const __half* srcB[2];
    uint32_t dBo[2];
    #pragma unroll
    for (int j = 0; j < 2; j++) {
        int idx = j * 512 + tid;
        int row = idx >> 2, kg = idx & 3;
        srcB[j] = Bf + (size_t)(n0 + row) * KD + kk0 + kg * 8;
        dBo[j]  = ASZ + (row * PITCH + kg * 8) * 2;
    }

    const uint32_t a_off = ((wm + (lane & 15)) * PITCH + ((lane >> 4) << 3)) * 2;
    const uint32_t b_off = ASZ + ((wn + ((lane >> 4) << 3) + (lane & 7)) * PITCH + (((lane >> 3) & 1) << 3)) * 2;

    float acc[2][8][4];
    #pragma unroll
    for (int i = 0; i < 2; i++)
        #pragma unroll
        for (int j = 0; j < 8; j++)
            #pragma unroll
            for (int q = 0; q < 4; q++) acc[i][j][q] = 0.f;

    cp16(sb0 + dA, srcA);
    cp16(sb0 + dBo[0], srcB[0]);
    cp16(sb0 + dBo[1], srcB[1]);
    asm volatile("cp.async.commit_group;" ::: "memory");
    srcA += BK; srcB[0] += BK; srcB[1] += BK;

    for (int i = 0; i < NCH; i++) {
        const int b = i & 1;
        if (i + 1 < NCH) {
            const uint32_t sn = sb0 + (1 - b) * STAGE;
            cp16(sn + dA, srcA);
            cp16(sn + dBo[0], srcB[0]);
            cp16(sn + dBo[1], srcB[1]);
            asm volatile("cp.async.commit_group;" ::: "memory");
            srcA += BK; srcB[0] += BK; srcB[1] += BK;
            asm volatile("cp.async.wait_group 1;" ::: "memory");
        } else {
            asm volatile("cp.async.wait_group 0;" ::: "memory");
        }
        __syncthreads();

        const uint32_t sa = sb0 + b * STAGE;
        #pragma unroll
        for (int ks = 0; ks < BK; ks += 16) {
            uint32_t afr[2][4], bfr[4][4];
            ldsm4(afr[0], sa + a_off + ks * 2);
            ldsm4(afr[1], sa + a_off + (16 * PITCH + ks) * 2);
            #pragma unroll
            for (int jn = 0; jn < 4; jn++)
                ldsm4(bfr[jn], sa + b_off + (jn * 16 * PITCH + ks) * 2);
            #pragma unroll
            for (int im = 0; im < 2; im++)
                #pragma unroll
                for (int jn = 0; jn < 4; jn++) {
                    mma16816(acc[im][2 * jn],     afr[im], &bfr[jn][0]);
                    mma16816(acc[im][2 * jn + 1], afr[im], &bfr[jn][2]);
                }
        }
        __syncthreads();
    }

    // gated atomic-add epilogue
    #pragma unroll
    for (int im = 0; im < 2; im++) {
        #pragma unroll
        for (int half = 0; half < 2; half++) {
            const int rloc = wm + im * 16 + half * 8 + (lane >> 2);
            if (rloc >= mrows) continue;
            const int   tok  = g_perm_token[m0 + rloc];
            const float gate = g_perm_gate[m0 + rloc];
            #pragma unroll
            for (int jn8 = 0; jn8 < 8; jn8++) {
                const int col = n0 + wn + jn8 * 8 + ((lane & 3) << 1);
                float* dst = outp + (size_t)tok * HDIM + col;
                atomicAdd(dst + 0, gate * acc[im][jn8][half * 2 + 0]);
                atomicAdd(dst + 1, gate * acc[im][jn8][half * 2 + 1]);
            }
        }
    }
}

// ================= launch =================
extern "C" void kernel_launch(void* const* d_in, const int* in_sizes, int n_in,
                              void* d_out, int out_size)
{
    const float* hs     = (const float*)d_in[0];
    const float* logits = (const float*)d_in[1];
    const float* w13    = (const float*)d_in[2];
    const float* w2     = (const float*)d_in[3];
    float* out = (float*)d_out;

    cudaFuncSetAttribute(gemm1_fused, cudaFuncAttributeMaxDynamicSharedMemorySize, SMEM_BYTES);
    cudaFuncSetAttribute(gemm2_f16,   cudaFuncAttributeMaxDynamicSharedMemorySize, SMEM_BYTES);

    zero_kernel<<<(T_TOK * HDIM / 4 + 255) / 256, 256>>>((float4*)out);
    route_kernel<<<1, 256>>>(logits);
    permA_kernel<<<(NASSIGN * HDIM / 4 + 255) / 256, 256>>>(hs);

    size_t n4_w13 = (size_t)NEXP * TWOI * HDIM / 4;
    size_t n4_w2  = (size_t)NEXP * HDIM * IDIM / 4;
    cvt16_kernel<0><<<(unsigned)((n4_w13 + 255) / 256), 256>>>((const float4*)w13, n4_w13);
    cvt16_kernel<1><<<(unsigned)((n4_w2  + 255) / 256), 256>>>((const float4*)w2,  n4_w2);

    gemm1_fused<<<dim3(MAXT, IDIM / 128), 512, SMEM_BYTES>>>(nullptr);
    gemm2_f16<<<dim3(MAXT, HDIM / BN, KSPLIT2), 512, SMEM_BYTES>>>(out);
}